// round 10
// baseline (speedup 1.0000x reference)
#include <cuda_runtime.h>
#include <cstdint>

// ---------------------------------------------------------------------------
// SpGraphAttentionLayer (GAT forward).  N=50000, D=128, O=128, R=64, E=1e6.
//
// Factored form:
//   u = a2 @ a  (320) ; c = u[256:320]
//   sdot_s[n] = x[n]·u[0:128] ; sdot_d[n] = x[n]·u[128:256]
//   t[e]      = emb[e]·c                      (src/dst independent!)
//   score[e]  = t[e] + sdot_s[src] + sdot_d[dst]
//   ee[e]     = exp(-leaky(score))
//   rs[n] = Σ ee ; w[n] = Σ ee·emb[e] (R^64) ; y[n] = Σ ee·x[dst] (R^128)
//   out[n] = rs>0 ? elu( [x[n], y[n]/rs, w[n]/rs] @ a^T ) : 0
//
// Aggregation: CSR build (hist/scan/scatter) + pure-gather node kernel.
// No floating-point atomics anywhere; 2 int atomics per edge total.
// ---------------------------------------------------------------------------

#define NMAX 50000
#define EMAX 1100000
#define GAT_ALPHA 0.2f

__device__ float g_sdot[(size_t)NMAX * 2];
__device__ float g_u[320];
__device__ float g_rowsum[NMAX];
__device__ float g_w[(size_t)NMAX * 64];
__device__ float g_y[(size_t)NMAX * 128];
__device__ float g_aT[320 * 128];
__device__ float g_t[EMAX];
__device__ int       g_cnt[NMAX];
__device__ int       g_off[NMAX + 1];
__device__ int       g_cur[NMAX];
__device__ long long g_adj[EMAX];          // (eid<<32) | dst

__device__ __forceinline__ void fma2(unsigned long long &acc,
                                     unsigned long long a, unsigned long long b) {
    asm("fma.rn.f32x2 %0, %1, %2, %0;" : "+l"(acc) : "l"(a), "l"(b));
}
__device__ __forceinline__ float2 unpack2(unsigned long long v) {
    float2 r;
    asm("mov.b64 {%0, %1}, %2;" : "=f"(r.x), "=f"(r.y) : "l"(v));
    return r;
}

// ---------------------------------------------------------------------------
__global__ void vec_kernel(const float* __restrict__ a, const float* __restrict__ a2) {
    __shared__ float a2s[128];
    int t = threadIdx.x;
    if (t < 128) a2s[t] = a2[t];
    __syncthreads();
    if (t < 320) {
        float acc = 0.f;
        #pragma unroll 8
        for (int o = 0; o < 128; o++) acc += a2s[o] * a[o * 320 + t];
        g_u[t] = acc;
    }
}

// ---------------------------------------------------------------------------
__global__ void transpose_a_kernel(const float* __restrict__ a) {
    int idx = blockIdx.x * 256 + threadIdx.x;
    if (idx < 320 * 128) {
        int k = idx >> 7, o = idx & 127;
        g_aT[idx] = a[o * 320 + k];
    }
}

// ---------------------------------------------------------------------------
__global__ void __launch_bounds__(128) sdot_kernel(const float* __restrict__ x, int N) {
    __shared__ float us[256];
    int t = threadIdx.x;
    us[t] = g_u[t];
    us[t + 128] = g_u[t + 128];
    __syncthreads();

    int n = blockIdx.x * 4 + (t >> 5);
    if (n >= N) return;
    int lane = t & 31;
    float ps = 0.f, pd = 0.f;
    #pragma unroll
    for (int j = 0; j < 4; j++) {
        float xv = x[(size_t)n * 128 + lane + 32 * j];
        ps += xv * us[lane + 32 * j];
        pd += xv * us[128 + lane + 32 * j];
    }
    #pragma unroll
    for (int off = 16; off; off >>= 1) {
        ps += __shfl_xor_sync(0xffffffffu, ps, off);
        pd += __shfl_xor_sync(0xffffffffu, pd, off);
    }
    if (lane == 0) { g_sdot[2 * n] = ps; g_sdot[2 * n + 1] = pd; }
}

// ---------------------------------------------------------------------------
// CSR build
// ---------------------------------------------------------------------------
__global__ void cnt_zero_kernel(int N) {
    int i = blockIdx.x * blockDim.x + threadIdx.x;
    if (i < N) g_cnt[i] = 0;
}

__global__ void hist_kernel(const int* __restrict__ e1, const int* __restrict__ e2,
                            int E1, int E2) {
    int E = E1 + E2;
    int stride = gridDim.x * blockDim.x;
    for (int e = blockIdx.x * blockDim.x + threadIdx.x; e < E; e += stride) {
        int s = (e < E1) ? e1[e] : e2[e - E1];
        atomicAdd(&g_cnt[s], 1);
    }
}

// single block, 1024 threads: exclusive scan of g_cnt -> g_off, g_cur
__global__ void __launch_bounds__(1024) scan_kernel(int N) {
    __shared__ int sums[1024];
    int t = threadIdx.x;
    int CH = (N + 1023) >> 10;
    int lo = t * CH;
    int hi = lo + CH; if (hi > N) hi = N; if (lo > N) lo = N;

    int s = 0;
    for (int i = lo; i < hi; i++) s += g_cnt[i];
    sums[t] = s;
    __syncthreads();

    for (int off = 1; off < 1024; off <<= 1) {
        int v = (t >= off) ? sums[t - off] : 0;
        __syncthreads();
        sums[t] += v;
        __syncthreads();
    }

    int run = (t > 0) ? sums[t - 1] : 0;
    for (int i = lo; i < hi; i++) {
        int c = g_cnt[i];
        g_off[i] = run;
        g_cur[i] = run;
        run += c;
    }
    if (t == 1023) g_off[N] = run;
}

__global__ void scatter_kernel(const int* __restrict__ e1, const int* __restrict__ e2,
                               int E1, int E2) {
    int E = E1 + E2;
    int stride = gridDim.x * blockDim.x;
    for (int e = blockIdx.x * blockDim.x + threadIdx.x; e < E; e += stride) {
        int s, d;
        if (e < E1) { s = e1[e]; d = e1[E1 + e]; }
        else { int g2 = e - E1; s = e2[g2]; d = e2[E2 + g2]; }
        int pos = atomicAdd(&g_cur[s], 1);
        g_adj[pos] = ((long long)e << 32) | (unsigned int)d;
    }
}

// ---------------------------------------------------------------------------
// passB: t[e] = emb[e]·c.  Streaming, coalesced, no atomics.
// Warp owns 16 edges/chunk; half-warp h handles edges 2i+h in phase i.
// ---------------------------------------------------------------------------
__global__ void __launch_bounds__(256) passB_kernel(
    const float* __restrict__ emb1, const float* __restrict__ emb2,
    int E1i, int E2i)
{
    const long long E1 = E1i, E2 = E2i;
    const long long E = E1 + E2;
    const long long CH = (E + 15) >> 4;

    const int lane = threadIdx.x & 31;
    const int sub  = lane & 15;
    const int half = lane >> 4;

    long long gwarp = (long long)blockIdx.x * (blockDim.x >> 5) + (threadIdx.x >> 5);
    const long long nwarps = (long long)gridDim.x * (blockDim.x >> 5);

    const float4 c4 = *(const float4*)(g_u + 256 + sub * 4);

    for (long long ch = gwarp; ch < CH; ch += nwarps) {
        const long long base = ch << 4;
        float sc_mine = 0.f;
        #pragma unroll
        for (int i = 0; i < 8; i++) {
            long long e = base + 2 * i + half;
            if (e >= E) e = E - 1;
            const float* ep = (e < E1) ? (emb1 + e * 64) : (emb2 + (e - E1) * 64);
            float4 em = __ldg((const float4*)ep + sub);
            float p = em.x * c4.x + em.y * c4.y + em.z * c4.z + em.w * c4.w;
            p += __shfl_xor_sync(0xffffffffu, p, 1);
            p += __shfl_xor_sync(0xffffffffu, p, 2);
            p += __shfl_xor_sync(0xffffffffu, p, 4);
            p += __shfl_xor_sync(0xffffffffu, p, 8);
            float s0 = __shfl_sync(0xffffffffu, p, 0);
            float s1 = __shfl_sync(0xffffffffu, p, 16);
            if (lane == 2 * i)     sc_mine = s0;
            if (lane == 2 * i + 1) sc_mine = s1;
        }
        if (lane < 16 && base + lane < E) g_t[base + lane] = sc_mine;
    }
}

// ---------------------------------------------------------------------------
// Node kernel: warp per node, pure gather, zero shuffne chains, zero FP atomics.
// Batch of 4 edges: 17 independent loads in flight (adj, 4x emb.64, 4x x.128,
// 4x t + 4x sdot uniform-broadcast). ee from scalars. One STG set per node.
// ---------------------------------------------------------------------------
__global__ void __launch_bounds__(256) node_kernel(
    const float* __restrict__ x, const float* __restrict__ emb1,
    const float* __restrict__ emb2, int E1, int N)
{
    const int warp = threadIdx.x >> 5;
    const int lane = threadIdx.x & 31;
    const int n = blockIdx.x * 8 + warp;
    if (n >= N) return;

    const int off0 = g_off[n];
    const int deg  = g_off[n + 1] - off0;
    const float ssn = g_sdot[2 * n];

    float2 wacc = make_float2(0.f, 0.f);
    float4 yacc = make_float4(0.f, 0.f, 0.f, 0.f);
    float rs = 0.f;

    for (int b = 0; b < deg; b += 4) {
        long long pk = (lane < 4 && b + lane < deg) ? g_adj[off0 + b + lane] : 0;

        float2 em[4];
        float4 xv[4];
        float  tt[4], sdd[4];
        #pragma unroll
        for (int i = 0; i < 4; i++) {
            long long p = __shfl_sync(0xffffffffu, pk, i);
            int dd = (int)(p & 0xffffffffLL);
            int ei = (int)((unsigned long long)p >> 32);
            const float* ep = (ei < E1) ? (emb1 + (size_t)ei * 64)
                                        : (emb2 + (size_t)(ei - E1) * 64);
            em[i]  = __ldg((const float2*)ep + lane);
            xv[i]  = __ldg((const float4*)(x + (size_t)dd * 128) + lane);
            tt[i]  = g_t[ei];              // uniform broadcast
            sdd[i] = g_sdot[2 * dd + 1];   // uniform broadcast
        }
        #pragma unroll
        for (int i = 0; i < 4; i++) {
            float sc = tt[i] + ssn + sdd[i];
            float pw = sc > 0.f ? sc : GAT_ALPHA * sc;
            float ee = (b + i < deg) ? __expf(-pw) : 0.f;
            rs += ee;
            wacc.x += ee * em[i].x; wacc.y += ee * em[i].y;
            yacc.x += ee * xv[i].x; yacc.y += ee * xv[i].y;
            yacc.z += ee * xv[i].z; yacc.w += ee * xv[i].w;
        }
    }

    *(float2*)(g_w + (size_t)n * 64 + lane * 2) = wacc;
    *(float4*)(g_y + (size_t)n * 128 + lane * 4) = yacc;
    if (lane == 0) g_rowsum[n] = rs;
}

// ---------------------------------------------------------------------------
// Final GEMM: out[64n x 128o] = elu( z @ a^T ), z = [x | y/rs | w/rs] (K=320).
// ---------------------------------------------------------------------------
__global__ void __launch_bounds__(256) final_kernel(
    const float* __restrict__ x, float* __restrict__ out, int N)
{
    __shared__ float2 z_sm[64 * 65];
    __shared__ float  a_sm[64 * 132];
    __shared__ float  inv_sm[64];

    const int tid = threadIdx.x;
    const int warp = tid >> 5, lane = tid & 31;
    const int n0 = blockIdx.x * 64;

    const int ob = (warp & 1) * 64;
    const int nb = (warp >> 1) * 16;
    const int nloc = nb + (lane >> 3) * 4;
    const int o0 = ob + (lane & 7) * 8;

    if (tid < 64) {
        float rs = (n0 + tid < N) ? g_rowsum[n0 + tid] : 0.f;
        inv_sm[tid] = rs > 0.f ? 1.f / rs : 0.f;
    }

    unsigned long long acc[4][4];
    #pragma unroll
    for (int j = 0; j < 4; j++)
        #pragma unroll
        for (int p = 0; p < 4; p++) acc[j][p] = 0ull;

    #pragma unroll
    for (int kc = 0; kc < 5; kc++) {
        __syncthreads();
        #pragma unroll
        for (int it = 0; it < 8; it++) {
            int i = tid + it * 256;
            int k = i >> 5, qq = i & 31;
            float4 av = *(const float4*)(g_aT + (size_t)(kc * 64 + k) * 128 + qq * 4);
            *(float4*)&a_sm[k * 132 + qq * 4] = av;
        }
        #pragma unroll
        for (int it = 0; it < 16; it++) {
            int i = tid + it * 256;
            int n = i >> 6, k = i & 63;
            float val = 0.f;
            if (n0 + n < N) {
                if (kc < 2)       val = x[(size_t)(n0 + n) * 128 + kc * 64 + k];
                else if (kc < 4)  val = g_y[(size_t)(n0 + n) * 128 + (kc - 2) * 64 + k] * inv_sm[n];
                else              val = g_w[(size_t)(n0 + n) * 64 + k] * inv_sm[n];
            }
            z_sm[n * 65 + k] = make_float2(val, val);
        }
        __syncthreads();

        #pragma unroll 8
        for (int k = 0; k < 64; k++) {
            ulonglong2 A01 = *(const ulonglong2*)&a_sm[k * 132 + o0];
            ulonglong2 A23 = *(const ulonglong2*)&a_sm[k * 132 + o0 + 4];
            #pragma unroll
            for (int j = 0; j < 4; j++) {
                unsigned long long zd = *(const unsigned long long*)&z_sm[(nloc + j) * 65 + k];
                fma2(acc[j][0], zd, A01.x);
                fma2(acc[j][1], zd, A01.y);
                fma2(acc[j][2], zd, A23.x);
                fma2(acc[j][3], zd, A23.y);
            }
        }
    }

    #pragma unroll
    for (int j = 0; j < 4; j++) {
        int n = n0 + nloc + j;
        if (n < N) {
            bool ok = inv_sm[nloc + j] > 0.f;
            float o[8];
            #pragma unroll
            for (int p = 0; p < 4; p++) {
                float2 f = unpack2(acc[j][p]);
                o[2 * p] = f.x; o[2 * p + 1] = f.y;
            }
            #pragma unroll
            for (int q = 0; q < 8; q++)
                o[q] = ok ? (o[q] > 0.f ? o[q] : expm1f(o[q])) : 0.f;
            float* dp = out + (size_t)n * 128 + o0;
            *(float4*)dp = make_float4(o[0], o[1], o[2], o[3]);
            *(float4*)(dp + 4) = make_float4(o[4], o[5], o[6], o[7]);
        }
    }
}

// ---------------------------------------------------------------------------
extern "C" void kernel_launch(void* const* d_in, const int* in_sizes, int n_in,
                              void* d_out, int out_size) {
    const float* x     = (const float*)d_in[0];
    const int*   edge1 = (const int*)  d_in[1];
    const float* emb1  = (const float*)d_in[2];
    const int*   edge2 = (const int*)  d_in[3];
    const float* emb2  = (const float*)d_in[4];
    const float* a     = (const float*)d_in[5];
    const float* a2    = (const float*)d_in[6];
    float* out = (float*)d_out;

    int N  = in_sizes[0] / 128;
    int E1 = in_sizes[1] / 2;
    int E2 = in_sizes[3] / 2;

    // ordered so launch #4 (the one ncu captures) is scatter_kernel
    cnt_zero_kernel<<<(N + 1023) / 1024, 1024>>>(N);
    hist_kernel<<<1024, 256>>>(edge1, edge2, E1, E2);
    scan_kernel<<<1, 1024>>>(N);
    scatter_kernel<<<1024, 256>>>(edge1, edge2, E1, E2);
    vec_kernel<<<1, 320>>>(a, a2);
    sdot_kernel<<<(N + 3) / 4, 128>>>(x, N);
    passB_kernel<<<592, 256>>>(emb1, emb2, E1, E2);
    node_kernel<<<(N + 7) / 8, 256>>>(x, emb1, emb2, E1, N);
    transpose_a_kernel<<<160, 256>>>(a);
    final_kernel<<<(N + 63) / 64, 256>>>(x, out, N);
}

// round 11
// speedup vs baseline: 1.0442x; 1.0442x over previous
#include <cuda_runtime.h>
#include <cstdint>

// ---------------------------------------------------------------------------
// SpGraphAttentionLayer (GAT forward).  N=50000, D=128, O=128, R=64, E=1e6.
//
// Factored form:
//   u = a2 @ a  (320) ; c = u[256:320]
//   sdot_s[n] = x[n]·u[0:128] ; sdot_d[n] = x[n]·u[128:256]
//   score[e]  = emb[e]·c + sdot_s[src] + sdot_d[dst]
//   ee[e]     = exp(-leaky(score))
//   rs[n] = Σ ee ; w[n] = Σ ee·emb[e] (R^64) ; y[n] = Σ ee·x[dst] (R^128)
//   out[n] = rs>0 ? elu( [x[n], y[n]/rs, w[n]/rs] @ a^T ) : 0
//
// Hybrid aggregation (emb read exactly once):
//   passA: stream emb -> ee (coalesced store) + scatter w (red.v4).
//   CSR build: hist/scan, scatter packs (ee,dst) per src.
//   node kernel: gather x[dst] (L2-resident) -> y + rs, plain stores.
// ---------------------------------------------------------------------------

#define NMAX 50000
#define EMAX 1100000
#define GAT_ALPHA 0.2f

__device__ float g_sdot[(size_t)NMAX * 2];
__device__ float g_u[320];
__device__ float g_rowsum[NMAX];
__device__ float g_w[(size_t)NMAX * 64];
__device__ float g_y[(size_t)NMAX * 128];
__device__ float g_aT[320 * 128];
__device__ float g_ee[EMAX];
__device__ int       g_cnt[NMAX];
__device__ int       g_off[NMAX + 1];
__device__ int       g_cur[NMAX];
__device__ long long g_adj[EMAX];          // (bits(ee)<<32) | dst

__device__ __forceinline__ void fma2(unsigned long long &acc,
                                     unsigned long long a, unsigned long long b) {
    asm("fma.rn.f32x2 %0, %1, %2, %0;" : "+l"(acc) : "l"(a), "l"(b));
}
__device__ __forceinline__ float2 unpack2(unsigned long long v) {
    float2 r;
    asm("mov.b64 {%0, %1}, %2;" : "=f"(r.x), "=f"(r.y) : "l"(v));
    return r;
}

// ---------------------------------------------------------------------------
__global__ void vec_kernel(const float* __restrict__ a, const float* __restrict__ a2) {
    __shared__ float a2s[128];
    int t = threadIdx.x;
    if (t < 128) a2s[t] = a2[t];
    __syncthreads();
    if (t < 320) {
        float acc = 0.f;
        #pragma unroll 8
        for (int o = 0; o < 128; o++) acc += a2s[o] * a[o * 320 + t];
        g_u[t] = acc;
    }
}

// ---------------------------------------------------------------------------
__global__ void __launch_bounds__(128) sdot_kernel(const float* __restrict__ x, int N) {
    __shared__ float us[256];
    int t = threadIdx.x;
    us[t] = g_u[t];
    us[t + 128] = g_u[t + 128];
    __syncthreads();

    int n = blockIdx.x * 4 + (t >> 5);
    if (n >= N) return;
    int lane = t & 31;
    float ps = 0.f, pd = 0.f;
    #pragma unroll
    for (int j = 0; j < 4; j++) {
        float xv = x[(size_t)n * 128 + lane + 32 * j];
        ps += xv * us[lane + 32 * j];
        pd += xv * us[128 + lane + 32 * j];
    }
    #pragma unroll
    for (int off = 16; off; off >>= 1) {
        ps += __shfl_xor_sync(0xffffffffu, ps, off);
        pd += __shfl_xor_sync(0xffffffffu, pd, off);
    }
    if (lane == 0) { g_sdot[2 * n] = ps; g_sdot[2 * n + 1] = pd; }
}

// ---------------------------------------------------------------------------
// zero g_w + g_cnt
// ---------------------------------------------------------------------------
__global__ void zero_kernel(int N) {
    int stride = gridDim.x * blockDim.x;
    int i = blockIdx.x * blockDim.x + threadIdx.x;
    int nw = N * 16;
    float4 z = make_float4(0.f, 0.f, 0.f, 0.f);
    for (int j = i; j < nw; j += stride) ((float4*)g_w)[j] = z;
    for (int j = i; j < N; j += stride) g_cnt[j] = 0;
}

// ---------------------------------------------------------------------------
// passA: stream emb once. Warp owns 16 edges/chunk; half-warp h handles
// edges 2i+h in phase i. Outputs: g_ee[e] (coalesced), w[src] += ee*emb
// (red.v4, emb register-resident). No slot atomics, no rowsum atomics.
// ---------------------------------------------------------------------------
__global__ void __launch_bounds__(256) passA_kernel(
    const int* __restrict__ edge1, const float* __restrict__ emb1,
    const int* __restrict__ edge2, const float* __restrict__ emb2,
    int E1i, int E2i)
{
    const long long E1 = E1i, E2 = E2i;
    const long long E = E1 + E2;
    const long long CH = (E + 15) >> 4;

    const int lane = threadIdx.x & 31;
    const int sub  = lane & 15;
    const int half = lane >> 4;

    long long gwarp = (long long)blockIdx.x * (blockDim.x >> 5) + (threadIdx.x >> 5);
    const long long nwarps = (long long)gridDim.x * (blockDim.x >> 5);

    const float4 c4 = *(const float4*)(g_u + 256 + sub * 4);

    for (long long ch = gwarp; ch < CH; ch += nwarps) {
        const long long base = ch << 4;

        long long ge = base + sub;
        long long gec = (ge < E) ? ge : (E - 1);
        int s, d;
        if (gec < E1) { s = edge1[gec]; d = edge1[E1 + gec]; }
        else { long long g2 = gec - E1; s = edge2[g2]; d = edge2[E2 + g2]; }
        float ssd = g_sdot[2 * s] + g_sdot[2 * d + 1];

        float4 em[8];
        float sc_mine = 0.f;
        #pragma unroll
        for (int i = 0; i < 8; i++) {
            long long e = base + 2 * i + half;
            if (e >= E) e = E - 1;
            const float* ep = (e < E1) ? (emb1 + e * 64) : (emb2 + (e - E1) * 64);
            em[i] = __ldg((const float4*)ep + sub);
            float p = em[i].x * c4.x + em[i].y * c4.y + em[i].z * c4.z + em[i].w * c4.w;
            p += __shfl_xor_sync(0xffffffffu, p, 1);
            p += __shfl_xor_sync(0xffffffffu, p, 2);
            p += __shfl_xor_sync(0xffffffffu, p, 4);
            p += __shfl_xor_sync(0xffffffffu, p, 8);
            float s0 = __shfl_sync(0xffffffffu, p, 0);
            float s1 = __shfl_sync(0xffffffffu, p, 16);
            if (lane == 2 * i)     sc_mine = s0;
            if (lane == 2 * i + 1) sc_mine = s1;
        }

        // softmax weight + coalesced ee store on lanes 0..15
        float ee = 0.f;
        if (lane < 16 && ge < E) {
            float sc = sc_mine + ssd;
            float pw = sc > 0.f ? sc : GAT_ALPHA * sc;
            ee = __expf(-pw);
            g_ee[ge] = ee;
        }

        // scatter w: phase i covers edges 2i (half 0) and 2i+1 (half 1)
        #pragma unroll
        for (int i = 0; i < 8; i++) {
            int j = 2 * i + half;
            float eej = __shfl_sync(0xffffffffu, ee, j);
            int   sij = __shfl_sync(0xffffffffu, s, j);
            float w0 = eej * em[i].x, w1 = eej * em[i].y;
            float w2 = eej * em[i].z, w3 = eej * em[i].w;
            float* wp = g_w + (size_t)sij * 64 + sub * 4;
            asm volatile("red.global.add.v4.f32 [%0], {%1, %2, %3, %4};"
                         :: "l"(wp), "f"(w0), "f"(w1), "f"(w2), "f"(w3) : "memory");
        }
    }
}

// ---------------------------------------------------------------------------
// CSR build
// ---------------------------------------------------------------------------
__global__ void hist_kernel(const int* __restrict__ e1, const int* __restrict__ e2,
                            int E1, int E2) {
    int E = E1 + E2;
    int stride = gridDim.x * blockDim.x;
    for (int e = blockIdx.x * blockDim.x + threadIdx.x; e < E; e += stride) {
        int s = (e < E1) ? e1[e] : e2[e - E1];
        atomicAdd(&g_cnt[s], 1);
    }
}

__global__ void __launch_bounds__(1024) scan_kernel(int N) {
    __shared__ int sums[1024];
    int t = threadIdx.x;
    int CH = (N + 1023) >> 10;
    int lo = t * CH;
    int hi = lo + CH; if (hi > N) hi = N; if (lo > N) lo = N;

    int s = 0;
    for (int i = lo; i < hi; i++) s += g_cnt[i];
    sums[t] = s;
    __syncthreads();

    for (int off = 1; off < 1024; off <<= 1) {
        int v = (t >= off) ? sums[t - off] : 0;
        __syncthreads();
        sums[t] += v;
        __syncthreads();
    }

    int run = (t > 0) ? sums[t - 1] : 0;
    for (int i = lo; i < hi; i++) {
        int c = g_cnt[i];
        g_off[i] = run;
        g_cur[i] = run;
        run += c;
    }
    if (t == 1023) g_off[N] = run;
}

// packs (ee, dst) into the CSR slot so the node kernel has zero indirection
__global__ void scatter_kernel(const int* __restrict__ e1, const int* __restrict__ e2,
                               int E1, int E2) {
    int E = E1 + E2;
    int stride = gridDim.x * blockDim.x;
    for (int e = blockIdx.x * blockDim.x + threadIdx.x; e < E; e += stride) {
        int s, d;
        if (e < E1) { s = e1[e]; d = e1[E1 + e]; }
        else { int g2 = e - E1; s = e2[g2]; d = e2[E2 + g2]; }
        float ee = g_ee[e];
        int pos = atomicAdd(&g_cur[s], 1);
        g_adj[pos] = ((long long)(unsigned int)__float_as_uint(ee) << 32)
                   | (unsigned int)d;
    }
}

// ---------------------------------------------------------------------------
// Node kernel: warp per node, pure gather of x[dst] (L2-resident).
// Batch of 8 edges with software-pipelined pk prefetch. Zero FP atomics.
// Invalid slots: pk=0 -> ee=0, dst=0 (x[0] L1-hot, adds 0).
// ---------------------------------------------------------------------------
__global__ void __launch_bounds__(256) node_kernel(const float* __restrict__ x, int N) {
    const int warp = threadIdx.x >> 5;
    const int lane = threadIdx.x & 31;
    const int n = blockIdx.x * 8 + warp;
    if (n >= N) return;

    const int off0 = g_off[n];
    const int deg  = g_off[n + 1] - off0;

    float4 acc = make_float4(0.f, 0.f, 0.f, 0.f);
    float rs = 0.f;

    long long pk = (lane < 8 && lane < deg) ? g_adj[off0 + lane] : 0;

    for (int b = 0; b < deg; b += 8) {
        long long pk_next = (lane < 8 && b + 8 + lane < deg) ? g_adj[off0 + b + 8 + lane] : 0;

        float eev[8];
        float4 xv[8];
        #pragma unroll
        for (int i = 0; i < 8; i++) {
            long long p = __shfl_sync(0xffffffffu, pk, i);
            int dd = (int)(p & 0xffffffffLL);
            eev[i] = __uint_as_float((unsigned int)((unsigned long long)p >> 32));
            xv[i] = __ldg((const float4*)(x + (size_t)dd * 128) + lane);
        }
        #pragma unroll
        for (int i = 0; i < 8; i++) {
            acc.x += eev[i] * xv[i].x;
            acc.y += eev[i] * xv[i].y;
            acc.z += eev[i] * xv[i].z;
            acc.w += eev[i] * xv[i].w;
            rs += eev[i];
        }
        pk = pk_next;
    }

    *(float4*)(g_y + (size_t)n * 128 + lane * 4) = acc;
    if (lane == 0) g_rowsum[n] = rs;
}

// ---------------------------------------------------------------------------
__global__ void transpose_a_kernel(const float* __restrict__ a) {
    int idx = blockIdx.x * 256 + threadIdx.x;
    if (idx < 320 * 128) {
        int k = idx >> 7, o = idx & 127;
        g_aT[idx] = a[o * 320 + k];
    }
}

// ---------------------------------------------------------------------------
// Final GEMM: out[64n x 128o] = elu( z @ a^T ), z = [x | y/rs | w/rs] (K=320).
// ---------------------------------------------------------------------------
__global__ void __launch_bounds__(256) final_kernel(
    const float* __restrict__ x, float* __restrict__ out, int N)
{
    __shared__ float2 z_sm[64 * 65];
    __shared__ float  a_sm[64 * 132];
    __shared__ float  inv_sm[64];

    const int tid = threadIdx.x;
    const int warp = tid >> 5, lane = tid & 31;
    const int n0 = blockIdx.x * 64;

    const int ob = (warp & 1) * 64;
    const int nb = (warp >> 1) * 16;
    const int nloc = nb + (lane >> 3) * 4;
    const int o0 = ob + (lane & 7) * 8;

    if (tid < 64) {
        float rs = (n0 + tid < N) ? g_rowsum[n0 + tid] : 0.f;
        inv_sm[tid] = rs > 0.f ? 1.f / rs : 0.f;
    }

    unsigned long long acc[4][4];
    #pragma unroll
    for (int j = 0; j < 4; j++)
        #pragma unroll
        for (int p = 0; p < 4; p++) acc[j][p] = 0ull;

    #pragma unroll
    for (int kc = 0; kc < 5; kc++) {
        __syncthreads();
        #pragma unroll
        for (int it = 0; it < 8; it++) {
            int i = tid + it * 256;
            int k = i >> 5, qq = i & 31;
            float4 av = *(const float4*)(g_aT + (size_t)(kc * 64 + k) * 128 + qq * 4);
            *(float4*)&a_sm[k * 132 + qq * 4] = av;
        }
        #pragma unroll
        for (int it = 0; it < 16; it++) {
            int i = tid + it * 256;
            int n = i >> 6, k = i & 63;
            float val = 0.f;
            if (n0 + n < N) {
                if (kc < 2)       val = x[(size_t)(n0 + n) * 128 + kc * 64 + k];
                else if (kc < 4)  val = g_y[(size_t)(n0 + n) * 128 + (kc - 2) * 64 + k] * inv_sm[n];
                else              val = g_w[(size_t)(n0 + n) * 64 + k] * inv_sm[n];
            }
            z_sm[n * 65 + k] = make_float2(val, val);
        }
        __syncthreads();

        #pragma unroll 8
        for (int k = 0; k < 64; k++) {
            ulonglong2 A01 = *(const ulonglong2*)&a_sm[k * 132 + o0];
            ulonglong2 A23 = *(const ulonglong2*)&a_sm[k * 132 + o0 + 4];
            #pragma unroll
            for (int j = 0; j < 4; j++) {
                unsigned long long zd = *(const unsigned long long*)&z_sm[(nloc + j) * 65 + k];
                fma2(acc[j][0], zd, A01.x);
                fma2(acc[j][1], zd, A01.y);
                fma2(acc[j][2], zd, A23.x);
                fma2(acc[j][3], zd, A23.y);
            }
        }
    }

    #pragma unroll
    for (int j = 0; j < 4; j++) {
        int n = n0 + nloc + j;
        if (n < N) {
            bool ok = inv_sm[nloc + j] > 0.f;
            float o[8];
            #pragma unroll
            for (int p = 0; p < 4; p++) {
                float2 f = unpack2(acc[j][p]);
                o[2 * p] = f.x; o[2 * p + 1] = f.y;
            }
            #pragma unroll
            for (int q = 0; q < 8; q++)
                o[q] = ok ? (o[q] > 0.f ? o[q] : expm1f(o[q])) : 0.f;
            float* dp = out + (size_t)n * 128 + o0;
            *(float4*)dp = make_float4(o[0], o[1], o[2], o[3]);
            *(float4*)(dp + 4) = make_float4(o[4], o[5], o[6], o[7]);
        }
    }
}

// ---------------------------------------------------------------------------
extern "C" void kernel_launch(void* const* d_in, const int* in_sizes, int n_in,
                              void* d_out, int out_size) {
    const float* x     = (const float*)d_in[0];
    const int*   edge1 = (const int*)  d_in[1];
    const float* emb1  = (const float*)d_in[2];
    const int*   edge2 = (const int*)  d_in[3];
    const float* emb2  = (const float*)d_in[4];
    const float* a     = (const float*)d_in[5];
    const float* a2    = (const float*)d_in[6];
    float* out = (float*)d_out;

    int N  = in_sizes[0] / 128;
    int E1 = in_sizes[1] / 2;
    int E2 = in_sizes[3] / 2;

    // ordered so launch #4 (the one ncu captures) is passA_kernel
    vec_kernel<<<1, 320>>>(a, a2);
    sdot_kernel<<<(N + 3) / 4, 128>>>(x, N);
    zero_kernel<<<1024, 256>>>(N);
    passA_kernel<<<592, 256>>>(edge1, emb1, edge2, emb2, E1, E2);
    hist_kernel<<<1024, 256>>>(edge1, edge2, E1, E2);
    scan_kernel<<<1, 1024>>>(N);
    scatter_kernel<<<1024, 256>>>(edge1, edge2, E1, E2);
    node_kernel<<<(N + 7) / 8, 256>>>(x, N);
    transpose_a_kernel<<<160, 256>>>(a);
    final_kernel<<<(N + 63) / 64, 256>>>(x, out, N);
}

// round 12
// speedup vs baseline: 1.0617x; 1.0168x over previous
#include <cuda_runtime.h>
#include <cstdint>

// ---------------------------------------------------------------------------
// SpGraphAttentionLayer (GAT forward).  N=50000, D=128, O=128, R=64, E=1e6.
//
// Factored form:
//   u = a2 @ a  (320) ; c = u[256:320]
//   sdot_s[n] = x[n]·u[0:128] ; sdot_d[n] = x[n]·u[128:256]
//   score[e]  = emb[e]·c + sdot_s[src] + sdot_d[dst]
//   ee[e]     = exp(-leaky(score))
//   rs[n] = Σ ee ; w[n] = Σ ee·emb[e] (R^64) ; y[n] = Σ ee·x[dst] (R^128)
//   out[n] = rs>0 ? elu( [x[n], y[n]/rs, w[n]/rs] @ a^T ) : 0
//
// Pipeline:
//   passA  : stream emb once -> ee (coalesced), w[src] += ee*emb (red.v4),
//            hist of src counts (fused).
//   scan   : offsets.  scatter: packs (ee,dst) per src.
//   final  : FUSED per 64-node block: gather y,rs from CSR into smem,
//            then K=320 GEMM + elu.  g_y eliminated entirely.
// ---------------------------------------------------------------------------

#define NMAX 50000
#define EMAX 1100000
#define GAT_ALPHA 0.2f

__device__ float g_sdot[(size_t)NMAX * 2];
__device__ float g_u[320];
__device__ float g_w[(size_t)NMAX * 64];
__device__ float g_aT[320 * 128];
__device__ float g_ee[EMAX];
__device__ int       g_cnt[NMAX];
__device__ int       g_off[NMAX + 1];
__device__ int       g_cur[NMAX];
__device__ long long g_adj[EMAX];          // (bits(ee)<<32) | dst

__device__ __forceinline__ void fma2(unsigned long long &acc,
                                     unsigned long long a, unsigned long long b) {
    asm("fma.rn.f32x2 %0, %1, %2, %0;" : "+l"(acc) : "l"(a), "l"(b));
}
__device__ __forceinline__ float2 unpack2(unsigned long long v) {
    float2 r;
    asm("mov.b64 {%0, %1}, %2;" : "=f"(r.x), "=f"(r.y) : "l"(v));
    return r;
}

// ---------------------------------------------------------------------------
__global__ void vec_kernel(const float* __restrict__ a, const float* __restrict__ a2) {
    __shared__ float a2s[128];
    int t = threadIdx.x;
    if (t < 128) a2s[t] = a2[t];
    __syncthreads();
    if (t < 320) {
        float acc = 0.f;
        #pragma unroll 8
        for (int o = 0; o < 128; o++) acc += a2s[o] * a[o * 320 + t];
        g_u[t] = acc;
    }
}

// ---------------------------------------------------------------------------
__global__ void __launch_bounds__(128) sdot_kernel(const float* __restrict__ x, int N) {
    __shared__ float us[256];
    int t = threadIdx.x;
    us[t] = g_u[t];
    us[t + 128] = g_u[t + 128];
    __syncthreads();

    int n = blockIdx.x * 4 + (t >> 5);
    if (n >= N) return;
    int lane = t & 31;
    float ps = 0.f, pd = 0.f;
    #pragma unroll
    for (int j = 0; j < 4; j++) {
        float xv = x[(size_t)n * 128 + lane + 32 * j];
        ps += xv * us[lane + 32 * j];
        pd += xv * us[128 + lane + 32 * j];
    }
    #pragma unroll
    for (int off = 16; off; off >>= 1) {
        ps += __shfl_xor_sync(0xffffffffu, ps, off);
        pd += __shfl_xor_sync(0xffffffffu, pd, off);
    }
    if (lane == 0) { g_sdot[2 * n] = ps; g_sdot[2 * n + 1] = pd; }
}

// ---------------------------------------------------------------------------
__global__ void zero_kernel(int N) {
    int stride = gridDim.x * blockDim.x;
    int i = blockIdx.x * blockDim.x + threadIdx.x;
    int nw = N * 16;
    float4 z = make_float4(0.f, 0.f, 0.f, 0.f);
    for (int j = i; j < nw; j += stride) ((float4*)g_w)[j] = z;
    for (int j = i; j < N; j += stride) g_cnt[j] = 0;
}

// ---------------------------------------------------------------------------
// passA: stream emb once. Warp owns 16 edges/chunk; half-warp h handles
// edges 2i+h in phase i. Outputs: g_ee[e] (coalesced), w[src] += ee*emb
// (red.v4), src histogram (fused).
// ---------------------------------------------------------------------------
__global__ void __launch_bounds__(256) passA_kernel(
    const int* __restrict__ edge1, const float* __restrict__ emb1,
    const int* __restrict__ edge2, const float* __restrict__ emb2,
    int E1i, int E2i)
{
    const long long E1 = E1i, E2 = E2i;
    const long long E = E1 + E2;
    const long long CH = (E + 15) >> 4;

    const int lane = threadIdx.x & 31;
    const int sub  = lane & 15;
    const int half = lane >> 4;

    long long gwarp = (long long)blockIdx.x * (blockDim.x >> 5) + (threadIdx.x >> 5);
    const long long nwarps = (long long)gridDim.x * (blockDim.x >> 5);

    const float4 c4 = *(const float4*)(g_u + 256 + sub * 4);

    for (long long ch = gwarp; ch < CH; ch += nwarps) {
        const long long base = ch << 4;

        long long ge = base + sub;
        long long gec = (ge < E) ? ge : (E - 1);
        int s, d;
        if (gec < E1) { s = edge1[gec]; d = edge1[E1 + gec]; }
        else { long long g2 = gec - E1; s = edge2[g2]; d = edge2[E2 + g2]; }
        float ssd = g_sdot[2 * s] + g_sdot[2 * d + 1];

        float4 em[8];
        float sc_mine = 0.f;
        #pragma unroll
        for (int i = 0; i < 8; i++) {
            long long e = base + 2 * i + half;
            if (e >= E) e = E - 1;
            const float* ep = (e < E1) ? (emb1 + e * 64) : (emb2 + (e - E1) * 64);
            em[i] = __ldg((const float4*)ep + sub);
            float p = em[i].x * c4.x + em[i].y * c4.y + em[i].z * c4.z + em[i].w * c4.w;
            p += __shfl_xor_sync(0xffffffffu, p, 1);
            p += __shfl_xor_sync(0xffffffffu, p, 2);
            p += __shfl_xor_sync(0xffffffffu, p, 4);
            p += __shfl_xor_sync(0xffffffffu, p, 8);
            float s0 = __shfl_sync(0xffffffffu, p, 0);
            float s1 = __shfl_sync(0xffffffffu, p, 16);
            if (lane == 2 * i)     sc_mine = s0;
            if (lane == 2 * i + 1) sc_mine = s1;
        }

        // softmax weight + coalesced ee store + hist on lanes 0..15
        float ee = 0.f;
        if (lane < 16 && ge < E) {
            float sc = sc_mine + ssd;
            float pw = sc > 0.f ? sc : GAT_ALPHA * sc;
            ee = __expf(-pw);
            g_ee[ge] = ee;
            atomicAdd(&g_cnt[s], 1);
        }

        // scatter w: phase i covers edges 2i (half 0) and 2i+1 (half 1)
        #pragma unroll
        for (int i = 0; i < 8; i++) {
            int j = 2 * i + half;
            float eej = __shfl_sync(0xffffffffu, ee, j);
            int   sij = __shfl_sync(0xffffffffu, s, j);
            float w0 = eej * em[i].x, w1 = eej * em[i].y;
            float w2 = eej * em[i].z, w3 = eej * em[i].w;
            float* wp = g_w + (size_t)sij * 64 + sub * 4;
            asm volatile("red.global.add.v4.f32 [%0], {%1, %2, %3, %4};"
                         :: "l"(wp), "f"(w0), "f"(w1), "f"(w2), "f"(w3) : "memory");
        }
    }
}

// ---------------------------------------------------------------------------
__global__ void __launch_bounds__(1024) scan_kernel(int N) {
    __shared__ int sums[1024];
    int t = threadIdx.x;
    int CH = (N + 1023) >> 10;
    int lo = t * CH;
    int hi = lo + CH; if (hi > N) hi = N; if (lo > N) lo = N;

    int s = 0;
    for (int i = lo; i < hi; i++) s += g_cnt[i];
    sums[t] = s;
    __syncthreads();

    for (int off = 1; off < 1024; off <<= 1) {
        int v = (t >= off) ? sums[t - off] : 0;
        __syncthreads();
        sums[t] += v;
        __syncthreads();
    }

    int run = (t > 0) ? sums[t - 1] : 0;
    for (int i = lo; i < hi; i++) {
        int c = g_cnt[i];
        g_off[i] = run;
        g_cur[i] = run;
        run += c;
    }
    if (t == 1023) g_off[N] = run;
}

__global__ void scatter_kernel(const int* __restrict__ e1, const int* __restrict__ e2,
                               int E1, int E2) {
    int E = E1 + E2;
    int stride = gridDim.x * blockDim.x;
    for (int e = blockIdx.x * blockDim.x + threadIdx.x; e < E; e += stride) {
        int s, d;
        if (e < E1) { s = e1[e]; d = e1[E1 + e]; }
        else { int g2 = e - E1; s = e2[g2]; d = e2[E2 + g2]; }
        float ee = g_ee[e];
        int pos = atomicAdd(&g_cur[s], 1);
        g_adj[pos] = ((long long)(unsigned int)__float_as_uint(ee) << 32)
                   | (unsigned int)d;
    }
}

// ---------------------------------------------------------------------------
__global__ void transpose_a_kernel(const float* __restrict__ a) {
    int idx = blockIdx.x * 256 + threadIdx.x;
    if (idx < 320 * 128) {
        int k = idx >> 7, o = idx & 127;
        g_aT[idx] = a[o * 320 + k];
    }
}

// ---------------------------------------------------------------------------
// FUSED final: block = 64 nodes, 256 threads.
// Phase 1: warp w gathers y,rs for nodes w*8..w*8+7 (uniform adj loads,
//          batched x-gather MLP=8, zero shuffles) into y_sm / inv_sm.
// Phase 2: GEMM out = elu(z @ a^T), z = [x | y/rs | w/rs], K=320 in 10
//          chunks of 32.  z duplicated {v,v} for f32x2; a from g_aT.
// ---------------------------------------------------------------------------
__global__ void __launch_bounds__(256) final_kernel(
    const float* __restrict__ x, float* __restrict__ out, int N)
{
    __shared__ float  y_sm[64 * 132];     // [n][k<128], pitch 132
    __shared__ float2 z_sm[64 * 33];      // [n][k32] duplicated pairs
    __shared__ float  a_sm[32 * 132];     // [k32][o]
    __shared__ float  inv_sm[64];

    const int tid = threadIdx.x;
    const int warp = tid >> 5, lane = tid & 31;
    const int n0 = blockIdx.x * 64;

    // ---- phase 1: gather ----
    #pragma unroll 1
    for (int q = 0; q < 8; q++) {
        int nloc = warp * 8 + q;
        int n = n0 + nloc;
        float4 acc = make_float4(0.f, 0.f, 0.f, 0.f);
        float rs = 0.f;
        if (n < N) {
            int off0 = g_off[n];
            int deg  = g_off[n + 1] - off0;
            for (int b = 0; b < deg; b += 8) {
                long long pk[8];
                #pragma unroll
                for (int i = 0; i < 8; i++)
                    pk[i] = (b + i < deg) ? g_adj[off0 + b + i] : 0;  // uniform
                #pragma unroll
                for (int i = 0; i < 8; i++) {
                    int dd = (int)(pk[i] & 0xffffffffLL);
                    float ee = __uint_as_float(
                        (unsigned int)((unsigned long long)pk[i] >> 32));
                    float4 xv = __ldg((const float4*)(x + (size_t)dd * 128) + lane);
                    acc.x += ee * xv.x; acc.y += ee * xv.y;
                    acc.z += ee * xv.z; acc.w += ee * xv.w;
                    rs += ee;
                }
            }
        }
        *(float4*)&y_sm[nloc * 132 + lane * 4] = acc;
        if (lane == 0) inv_sm[nloc] = rs;
    }
    __syncthreads();
    if (tid < 64) {
        float rsv = inv_sm[tid];
        inv_sm[tid] = rsv > 0.f ? 1.f / rsv : 0.f;
    }

    // ---- phase 2: GEMM ----
    const int ob = (warp & 1) * 64;
    const int nb = (warp >> 1) * 16;
    const int nloc2 = nb + (lane >> 3) * 4;
    const int o0 = ob + (lane & 7) * 8;

    unsigned long long acc[4][4];
    #pragma unroll
    for (int j = 0; j < 4; j++)
        #pragma unroll
        for (int p = 0; p < 4; p++) acc[j][p] = 0ull;

    #pragma unroll 1
    for (int kc = 0; kc < 10; kc++) {
        __syncthreads();
        // stage a chunk: 32k x 128o (1024 float4)
        #pragma unroll
        for (int it = 0; it < 4; it++) {
            int i = tid + it * 256;
            int k = i >> 5, qq = i & 31;
            float4 av = *(const float4*)(g_aT + (size_t)(kc * 32 + k) * 128 + qq * 4);
            *(float4*)&a_sm[k * 132 + qq * 4] = av;
        }
        // stage z chunk: 64n x 32k, duplicated
        #pragma unroll
        for (int it = 0; it < 8; it++) {
            int i = tid + it * 256;
            int n = i >> 5, k = i & 31;
            int gk = kc * 32 + k;
            float val = 0.f;
            if (n0 + n < N) {
                if (gk < 128)       val = x[(size_t)(n0 + n) * 128 + gk];
                else if (gk < 256)  val = y_sm[n * 132 + gk - 128] * inv_sm[n];
                else                val = g_w[(size_t)(n0 + n) * 64 + gk - 256] * inv_sm[n];
            }
            z_sm[n * 33 + k] = make_float2(val, val);
        }
        __syncthreads();

        #pragma unroll 8
        for (int k = 0; k < 32; k++) {
            ulonglong2 A01 = *(const ulonglong2*)&a_sm[k * 132 + o0];
            ulonglong2 A23 = *(const ulonglong2*)&a_sm[k * 132 + o0 + 4];
            #pragma unroll
            for (int j = 0; j < 4; j++) {
                unsigned long long zd = *(const unsigned long long*)&z_sm[(nloc2 + j) * 33 + k];
                fma2(acc[j][0], zd, A01.x);
                fma2(acc[j][1], zd, A01.y);
                fma2(acc[j][2], zd, A23.x);
                fma2(acc[j][3], zd, A23.y);
            }
        }
    }

    #pragma unroll
    for (int j = 0; j < 4; j++) {
        int n = n0 + nloc2 + j;
        if (n < N) {
            bool ok = inv_sm[nloc2 + j] > 0.f;
            float o[8];
            #pragma unroll
            for (int p = 0; p < 4; p++) {
                float2 f = unpack2(acc[j][p]);
                o[2 * p] = f.x; o[2 * p + 1] = f.y;
            }
            #pragma unroll
            for (int q = 0; q < 8; q++)
                o[q] = ok ? (o[q] > 0.f ? o[q] : expm1f(o[q])) : 0.f;
            float* dp = out + (size_t)n * 128 + o0;
            *(float4*)dp = make_float4(o[0], o[1], o[2], o[3]);
            *(float4*)(dp + 4) = make_float4(o[4], o[5], o[6], o[7]);
        }
    }
}

// ---------------------------------------------------------------------------
extern "C" void kernel_launch(void* const* d_in, const int* in_sizes, int n_in,
                              void* d_out, int out_size) {
    const float* x     = (const float*)d_in[0];
    const int*   edge1 = (const int*)  d_in[1];
    const float* emb1  = (const float*)d_in[2];
    const int*   edge2 = (const int*)  d_in[3];
    const float* emb2  = (const float*)d_in[4];
    const float* a     = (const float*)d_in[5];
    const float* a2    = (const float*)d_in[6];
    float* out = (float*)d_out;

    int N  = in_sizes[0] / 128;
    int E1 = in_sizes[1] / 2;
    int E2 = in_sizes[3] / 2;

    // launch #4 (the one ncu captures) = passA_kernel
    vec_kernel<<<1, 320>>>(a, a2);
    sdot_kernel<<<(N + 3) / 4, 128>>>(x, N);
    zero_kernel<<<1024, 256>>>(N);
    passA_kernel<<<592, 256>>>(edge1, emb1, edge2, emb2, E1, E2);
    scan_kernel<<<1, 1024>>>(N);
    scatter_kernel<<<1024, 256>>>(edge1, edge2, E1, E2);
    transpose_a_kernel<<<160, 256>>>(a);
    final_kernel<<<(N + 63) / 64, 256>>>(x, out, N);
}

// round 13
// speedup vs baseline: 1.2339x; 1.1622x over previous
#include <cuda_runtime.h>
#include <cstdint>

// ---------------------------------------------------------------------------
// SpGraphAttentionLayer (GAT forward).  N=50000, D=128, O=128, R=64, E=1e6.
//
// Factored form:
//   u = a2 @ a  (320) ; c = u[256:320]
//   sdot_s[n] = x[n]·u[0:128] ; sdot_d[n] = x[n]·u[128:256]
//   score[e]  = emb[e]·c + sdot_s[src] + sdot_d[dst]
//   ee[e]     = exp(-leaky(score))
//   rs[n] = Σ ee ; w[n] = Σ ee·emb[e] (R^64) ; y[n] = Σ ee·x[dst] (R^128)
//   out[n] = rs>0 ? elu( [x[n], y[n]/rs, w[n]/rs] @ a^T ) : 0
//
// Pipeline:
//   passA  : stream emb once -> ee, w[src] += ee*emb (red.v4), hist (fused)
//   scan/scatter : CSR with (ee,dst) packed
//   node   : gather y,rs (MLP=16 x-gather)
//   final  : 128n x 128o x K320 GEMM, thread tile 8n x 8o
// ---------------------------------------------------------------------------

#define NMAX 50000
#define EMAX 1100000
#define GAT_ALPHA 0.2f

__device__ float g_sdot[(size_t)NMAX * 2];
__device__ float g_u[320];
__device__ float g_rowsum[NMAX];
__device__ float g_w[(size_t)NMAX * 64];
__device__ float g_y[(size_t)NMAX * 128];
__device__ float g_aT[320 * 128];
__device__ float g_ee[EMAX];
__device__ int       g_cnt[NMAX];
__device__ int       g_off[NMAX + 1];
__device__ int       g_cur[NMAX];
__device__ long long g_adj[EMAX];          // (bits(ee)<<32) | dst

__device__ __forceinline__ void fma2(unsigned long long &acc,
                                     unsigned long long a, unsigned long long b) {
    asm("fma.rn.f32x2 %0, %1, %2, %0;" : "+l"(acc) : "l"(a), "l"(b));
}
__device__ __forceinline__ float2 unpack2(unsigned long long v) {
    float2 r;
    asm("mov.b64 {%0, %1}, %2;" : "=f"(r.x), "=f"(r.y) : "l"(v));
    return r;
}

// ---------------------------------------------------------------------------
__global__ void vec_kernel(const float* __restrict__ a, const float* __restrict__ a2) {
    __shared__ float a2s[128];
    int t = threadIdx.x;
    if (t < 128) a2s[t] = a2[t];
    __syncthreads();
    if (t < 320) {
        float acc = 0.f;
        #pragma unroll 8
        for (int o = 0; o < 128; o++) acc += a2s[o] * a[o * 320 + t];
        g_u[t] = acc;
    }
}

// ---------------------------------------------------------------------------
__global__ void __launch_bounds__(128) sdot_kernel(const float* __restrict__ x, int N) {
    __shared__ float us[256];
    int t = threadIdx.x;
    us[t] = g_u[t];
    us[t + 128] = g_u[t + 128];
    __syncthreads();

    int n = blockIdx.x * 4 + (t >> 5);
    if (n >= N) return;
    int lane = t & 31;
    float ps = 0.f, pd = 0.f;
    #pragma unroll
    for (int j = 0; j < 4; j++) {
        float xv = x[(size_t)n * 128 + lane + 32 * j];
        ps += xv * us[lane + 32 * j];
        pd += xv * us[128 + lane + 32 * j];
    }
    #pragma unroll
    for (int off = 16; off; off >>= 1) {
        ps += __shfl_xor_sync(0xffffffffu, ps, off);
        pd += __shfl_xor_sync(0xffffffffu, pd, off);
    }
    if (lane == 0) { g_sdot[2 * n] = ps; g_sdot[2 * n + 1] = pd; }
}

// ---------------------------------------------------------------------------
__global__ void zero_kernel(int N) {
    int stride = gridDim.x * blockDim.x;
    int i = blockIdx.x * blockDim.x + threadIdx.x;
    int nw = N * 16;
    float4 z = make_float4(0.f, 0.f, 0.f, 0.f);
    for (int j = i; j < nw; j += stride) ((float4*)g_w)[j] = z;
    for (int j = i; j < N; j += stride) g_cnt[j] = 0;
}

// ---------------------------------------------------------------------------
// passA: stream emb once. Outputs: g_ee (coalesced), w[src] += ee*emb (red.v4),
// src histogram (fused).
// ---------------------------------------------------------------------------
__global__ void __launch_bounds__(256) passA_kernel(
    const int* __restrict__ edge1, const float* __restrict__ emb1,
    const int* __restrict__ edge2, const float* __restrict__ emb2,
    int E1i, int E2i)
{
    const long long E1 = E1i, E2 = E2i;
    const long long E = E1 + E2;
    const long long CH = (E + 15) >> 4;

    const int lane = threadIdx.x & 31;
    const int sub  = lane & 15;
    const int half = lane >> 4;

    long long gwarp = (long long)blockIdx.x * (blockDim.x >> 5) + (threadIdx.x >> 5);
    const long long nwarps = (long long)gridDim.x * (blockDim.x >> 5);

    const float4 c4 = *(const float4*)(g_u + 256 + sub * 4);

    for (long long ch = gwarp; ch < CH; ch += nwarps) {
        const long long base = ch << 4;

        long long ge = base + sub;
        long long gec = (ge < E) ? ge : (E - 1);
        int s, d;
        if (gec < E1) { s = edge1[gec]; d = edge1[E1 + gec]; }
        else { long long g2 = gec - E1; s = edge2[g2]; d = edge2[E2 + g2]; }
        float ssd = g_sdot[2 * s] + g_sdot[2 * d + 1];

        float4 em[8];
        float sc_mine = 0.f;
        #pragma unroll
        for (int i = 0; i < 8; i++) {
            long long e = base + 2 * i + half;
            if (e >= E) e = E - 1;
            const float* ep = (e < E1) ? (emb1 + e * 64) : (emb2 + (e - E1) * 64);
            em[i] = __ldg((const float4*)ep + sub);
            float p = em[i].x * c4.x + em[i].y * c4.y + em[i].z * c4.z + em[i].w * c4.w;
            p += __shfl_xor_sync(0xffffffffu, p, 1);
            p += __shfl_xor_sync(0xffffffffu, p, 2);
            p += __shfl_xor_sync(0xffffffffu, p, 4);
            p += __shfl_xor_sync(0xffffffffu, p, 8);
            float s0 = __shfl_sync(0xffffffffu, p, 0);
            float s1 = __shfl_sync(0xffffffffu, p, 16);
            if (lane == 2 * i)     sc_mine = s0;
            if (lane == 2 * i + 1) sc_mine = s1;
        }

        float ee = 0.f;
        if (lane < 16 && ge < E) {
            float sc = sc_mine + ssd;
            float pw = sc > 0.f ? sc : GAT_ALPHA * sc;
            ee = __expf(-pw);
            g_ee[ge] = ee;
            atomicAdd(&g_cnt[s], 1);
        }

        #pragma unroll
        for (int i = 0; i < 8; i++) {
            int j = 2 * i + half;
            float eej = __shfl_sync(0xffffffffu, ee, j);
            int   sij = __shfl_sync(0xffffffffu, s, j);
            float w0 = eej * em[i].x, w1 = eej * em[i].y;
            float w2 = eej * em[i].z, w3 = eej * em[i].w;
            float* wp = g_w + (size_t)sij * 64 + sub * 4;
            asm volatile("red.global.add.v4.f32 [%0], {%1, %2, %3, %4};"
                         :: "l"(wp), "f"(w0), "f"(w1), "f"(w2), "f"(w3) : "memory");
        }
    }
}

// ---------------------------------------------------------------------------
__global__ void __launch_bounds__(1024) scan_kernel(int N) {
    __shared__ int sums[1024];
    int t = threadIdx.x;
    int CH = (N + 1023) >> 10;
    int lo = t * CH;
    int hi = lo + CH; if (hi > N) hi = N; if (lo > N) lo = N;

    int s = 0;
    for (int i = lo; i < hi; i++) s += g_cnt[i];
    sums[t] = s;
    __syncthreads();

    for (int off = 1; off < 1024; off <<= 1) {
        int v = (t >= off) ? sums[t - off] : 0;
        __syncthreads();
        sums[t] += v;
        __syncthreads();
    }

    int run = (t > 0) ? sums[t - 1] : 0;
    for (int i = lo; i < hi; i++) {
        int c = g_cnt[i];
        g_off[i] = run;
        g_cur[i] = run;
        run += c;
    }
    if (t == 1023) g_off[N] = run;
}

__global__ void scatter_kernel(const int* __restrict__ e1, const int* __restrict__ e2,
                               int E1, int E2) {
    int E = E1 + E2;
    int stride = gridDim.x * blockDim.x;
    for (int e = blockIdx.x * blockDim.x + threadIdx.x; e < E; e += stride) {
        int s, d;
        if (e < E1) { s = e1[e]; d = e1[E1 + e]; }
        else { int g2 = e - E1; s = e2[g2]; d = e2[E2 + g2]; }
        float ee = g_ee[e];
        int pos = atomicAdd(&g_cur[s], 1);
        g_adj[pos] = ((long long)(unsigned int)__float_as_uint(ee) << 32)
                   | (unsigned int)d;
    }
}

// ---------------------------------------------------------------------------
__global__ void transpose_a_kernel(const float* __restrict__ a) {
    int idx = blockIdx.x * 256 + threadIdx.x;
    if (idx < 320 * 128) {
        int k = idx >> 7, o = idx & 127;
        g_aT[idx] = a[o * 320 + k];
    }
}

// ---------------------------------------------------------------------------
// Node kernel: warp per node. Batches of 16 edges (MLP=16 x-gather), next pk
// batch prefetched during accumulation. Zero FP atomics, plain stores.
// ---------------------------------------------------------------------------
__global__ void __launch_bounds__(256) node_kernel(const float* __restrict__ x, int N) {
    const int warp = threadIdx.x >> 5;
    const int lane = threadIdx.x & 31;
    const int n = blockIdx.x * 8 + warp;
    if (n >= N) return;

    const int off0 = g_off[n];
    const int deg  = g_off[n + 1] - off0;

    float4 acc = make_float4(0.f, 0.f, 0.f, 0.f);
    float rs = 0.f;

    long long pk = (lane < 16 && lane < deg) ? g_adj[off0 + lane] : 0;

    for (int b = 0; b < deg; b += 16) {
        long long pk_next = (lane < 16 && b + 16 + lane < deg)
                          ? g_adj[off0 + b + 16 + lane] : 0;

        float eev[16];
        float4 xv[16];
        #pragma unroll
        for (int i = 0; i < 16; i++) {
            long long p = __shfl_sync(0xffffffffu, pk, i);
            int dd = (int)(p & 0xffffffffLL);
            eev[i] = __uint_as_float((unsigned int)((unsigned long long)p >> 32));
            xv[i] = __ldg((const float4*)(x + (size_t)dd * 128) + lane);
        }
        #pragma unroll
        for (int i = 0; i < 16; i++) {
            acc.x += eev[i] * xv[i].x;
            acc.y += eev[i] * xv[i].y;
            acc.z += eev[i] * xv[i].z;
            acc.w += eev[i] * xv[i].w;
            rs += eev[i];
        }
        pk = pk_next;
    }

    *(float4*)(g_y + (size_t)n * 128 + lane * 4) = acc;
    if (lane == 0) g_rowsum[n] = rs;
}

// ---------------------------------------------------------------------------
// Final GEMM: 128n x 128o per block, 256 threads, thread tile 8n x 8o.
// K = 320 in 20 chunks of 16; chunk source: kc<8 -> x, kc<16 -> y, else w.
// z stored duplicated {v,v}; a-pairs are real f32x2 (from LDS.128).
// ---------------------------------------------------------------------------
__global__ void __launch_bounds__(256, 2) final_kernel(
    const float* __restrict__ x, float* __restrict__ out, int N)
{
    __shared__ float2 z_sm[128 * 17];     // [n][k] duplicated pairs, pitch 17
    __shared__ float  a_sm[16 * 132];     // [k][o], pitch 132
    __shared__ float  inv_sm[128];

    const int tid = threadIdx.x;
    const int warp = tid >> 5, lane = tid & 31;
    const int n0 = blockIdx.x * 128;

    const int nb = (warp >> 1) * 32 + (lane >> 3) * 8;  // 8 nodes: nb..nb+7
    const int ob = (warp & 1) * 64 + (lane & 7) * 8;    // 8 outs:  ob..ob+7

    if (tid < 128) {
        float rs = (n0 + tid < N) ? g_rowsum[n0 + tid] : 0.f;
        inv_sm[tid] = rs > 0.f ? 1.f / rs : 0.f;
    }

    unsigned long long acc[8][4];
    #pragma unroll
    for (int j = 0; j < 8; j++)
        #pragma unroll
        for (int p = 0; p < 4; p++) acc[j][p] = 0ull;

    #pragma unroll 1
    for (int kc = 0; kc < 20; kc++) {
        __syncthreads();
        // stage a chunk: 16k x 128o = 512 float4
        {
            #pragma unroll
            for (int it = 0; it < 2; it++) {
                int i = tid + it * 256;
                int k = i >> 5, qq = i & 31;
                float4 av = *(const float4*)(g_aT + (size_t)(kc * 16 + k) * 128 + qq * 4);
                *(float4*)&a_sm[k * 132 + qq * 4] = av;
            }
        }
        // stage z chunk: 128n x 16k (as 512 float4 source slots), duplicated
        {
            #pragma unroll
            for (int it = 0; it < 2; it++) {
                int i = tid + it * 256;
                int n = i >> 2, kq = i & 3;        // 4 float4 per node-chunk
                float4 v = make_float4(0.f, 0.f, 0.f, 0.f);
                if (n0 + n < N) {
                    if (kc < 8) {
                        v = *(const float4*)(x + (size_t)(n0 + n) * 128 + kc * 16 + kq * 4);
                    } else if (kc < 16) {
                        v = *(const float4*)(g_y + (size_t)(n0 + n) * 128 + (kc - 8) * 16 + kq * 4);
                        float iv = inv_sm[n];
                        v.x *= iv; v.y *= iv; v.z *= iv; v.w *= iv;
                    } else {
                        v = *(const float4*)(g_w + (size_t)(n0 + n) * 64 + (kc - 16) * 16 + kq * 4);
                        float iv = inv_sm[n];
                        v.x *= iv; v.y *= iv; v.z *= iv; v.w *= iv;
                    }
                }
                float2* zp = &z_sm[n * 17 + kq * 4];
                zp[0] = make_float2(v.x, v.x);
                zp[1] = make_float2(v.y, v.y);
                zp[2] = make_float2(v.z, v.z);
                zp[3] = make_float2(v.w, v.w);
            }
        }
        __syncthreads();

        #pragma unroll
        for (int k = 0; k < 16; k++) {
            ulonglong2 A01 = *(const ulonglong2*)&a_sm[k * 132 + ob];
            ulonglong2 A23 = *(const ulonglong2*)&a_sm[k * 132 + ob + 4];
            #pragma unroll
            for (int j = 0; j < 8; j++) {
                unsigned long long zd = *(const unsigned long long*)&z_sm[(nb + j) * 17 + k];
                fma2(acc[j][0], zd, A01.x);
                fma2(acc[j][1], zd, A01.y);
                fma2(acc[j][2], zd, A23.x);
                fma2(acc[j][3], zd, A23.y);
            }
        }
    }

    // epilogue
    #pragma unroll
    for (int j = 0; j < 8; j++) {
        int n = n0 + nb + j;
        if (n < N) {
            bool ok = inv_sm[nb + j] > 0.f;
            float o[8];
            #pragma unroll
            for (int p = 0; p < 4; p++) {
                float2 f = unpack2(acc[j][p]);
                o[2 * p] = f.x; o[2 * p + 1] = f.y;
            }
            #pragma unroll
            for (int q = 0; q < 8; q++)
                o[q] = ok ? (o[q] > 0.f ? o[q] : expm1f(o[q])) : 0.f;
            float* dp = out + (size_t)n * 128 + ob;
            *(float4*)dp = make_float4(o[0], o[1], o[2], o[3]);
            *(float4*)(dp + 4) = make_float4(o[4], o[5], o[6], o[7]);
        }
    }
}

// ---------------------------------------------------------------------------
extern "C" void kernel_launch(void* const* d_in, const int* in_sizes, int n_in,
                              void* d_out, int out_size) {
    const float* x     = (const float*)d_in[0];
    const int*   edge1 = (const int*)  d_in[1];
    const float* emb1  = (const float*)d_in[2];
    const int*   edge2 = (const int*)  d_in[3];
    const float* emb2  = (const float*)d_in[4];
    const float* a     = (const float*)d_in[5];
    const float* a2    = (const float*)d_in[6];
    float* out = (float*)d_out;

    int N  = in_sizes[0] / 128;
    int E1 = in_sizes[1] / 2;
    int E2 = in_sizes[3] / 2;

    // launch #4 (the one ncu captures) = passA_kernel
    vec_kernel<<<1, 320>>>(a, a2);
    sdot_kernel<<<(N + 3) / 4, 128>>>(x, N);
    zero_kernel<<<1024, 256>>>(N);
    passA_kernel<<<592, 256>>>(edge1, emb1, edge2, emb2, E1, E2);
    scan_kernel<<<1, 1024>>>(N);
    scatter_kernel<<<1024, 256>>>(edge1, edge2, E1, E2);
    transpose_a_kernel<<<160, 256>>>(a);
    node_kernel<<<(N + 7) / 8, 256>>>(x, N);
    final_kernel<<<(N + 127) / 128, 256>>>(x, out, N);
}